// round 17
// baseline (speedup 1.0000x reference)
#include <cuda_runtime.h>
#include <cstdint>

#define ITEMS_TOTAL 50000
#define DIM         64
#define BATCH       16
#define NPG         50
#define VEC8_PER_ROW (DIM / 8)   // 8 x 32B chunks per row
#define ROWS_PER_CTA 32
#define THREADS      256         // 32 rows x 8 lanes (32B per lane)
#define N8           (ITEMS_TOTAL * VEC8_PER_ROW)   // 400,000 float8 per slice

// R5 structure with 256-bit loads/stores (sm_100+ v8.f32): 8 lanes x 32B per
// row, halving store-path instruction count per byte. Prologue identical to
// the proven best kernel.

struct f8 { float4 a, b; };

__device__ __forceinline__ f8 ldg256(const void* p) {
    f8 v;
    asm volatile("ld.global.nc.v8.f32 {%0,%1,%2,%3,%4,%5,%6,%7}, [%8];"
                 : "=f"(v.a.x), "=f"(v.a.y), "=f"(v.a.z), "=f"(v.a.w),
                   "=f"(v.b.x), "=f"(v.b.y), "=f"(v.b.z), "=f"(v.b.w)
                 : "l"(p));
    return v;
}

__device__ __forceinline__ void stg256(void* p, const f8& v) {
    asm volatile("st.global.cs.v8.f32 [%0], {%1,%2,%3,%4,%5,%6,%7,%8};"
                 :: "l"(p),
                    "f"(v.a.x), "f"(v.a.y), "f"(v.a.z), "f"(v.a.w),
                    "f"(v.b.x), "f"(v.b.y), "f"(v.b.z), "f"(v.b.w)
                 : "memory");
}

__global__ void __launch_bounds__(THREADS)
fused_kernel(const float* __restrict__ emb,        // (ITEMS_TOTAL, DIM)
             const float* __restrict__ feat,       // (BATCH*NPG, DIM)
             const float* __restrict__ alpha,      // (ITEMS_TOTAL, 1)
             const void*  __restrict__ nodes_raw,  // int32 or int64, 800 entries
             float*       __restrict__ out) {      // (BATCH, ITEMS_TOTAL, DIM)
    __shared__ int s_stage[BATCH * NPG];            // raw first 3200 bytes
    __shared__ int s_idx[BATCH * NPG];              // node indices as int32
    __shared__ int s_pos[ROWS_PER_CTA][BATCH + 1];  // last pos per (row,b); pad
    __shared__ int s_not64;
    __shared__ int s_any;

    const int tid   = threadIdx.x;
    const int rslot = tid >> 3;                     // 0..31 local row
    const int lane  = tid & 7;                      // 0..7, 32B each
    const int row_base = (int)blockIdx.x * ROWS_PER_CTA;
    const int row  = row_base + rslot;
    const bool row_ok = (row < ITEMS_TOTAL);

    // ---- Prefetch emb chunk (32B) ahead of the smem phases ----
    const long long t8 = (long long)row * VEC8_PER_ROW + lane;
    f8 v;
    if (row_ok) v = ldg256(emb + t8 * 8);

    const int* a32 = (const int*)nodes_raw;
    if (tid == 0) { s_not64 = 0; s_any = 0; }

    // Phase 1a: stage first 3200 bytes (valid under both dtypes).
    for (int k = tid; k < BATCH * NPG; k += THREADS) s_stage[k] = a32[k];
    __syncthreads();

    // Phase 1b: dtype detection — int64 LE with values < 50000 has all-zero
    // high words in the first 400 pairs.
    for (int k = tid; k < 400; k += THREADS) {
        if (s_stage[2 * k + 1] != 0) s_not64 = 1;   // benign race
    }
    __syncthreads();
    const bool is64 = (s_not64 == 0);

    // Phase 1c: compact to int32; flag if any node falls in our row window.
    for (int k = tid; k < BATCH * NPG; k += THREADS) {
        int val;
        if (is64) {
            val = (k < 400) ? s_stage[2 * k] : a32[2 * k];  // int64 buf = 6400 B
        } else {
            val = s_stage[k];
        }
        s_idx[k] = val;
        if ((unsigned)(val - row_base) < (unsigned)ROWS_PER_CTA) s_any = 1;
    }
    __syncthreads();

    if (s_any) {
        // Phase 2: each thread scans TWO graphs (lane, lane+8) for its row.
        {
            int b0 = lane, b1 = lane + 8;
            int p0 = -1, p1 = -1;
            const int base0 = b0 * NPG, base1 = b1 * NPG;
#pragma unroll 10
            for (int jj = 0; jj < NPG; jj++) {
                if (s_idx[base0 + jj] == row) p0 = base0 + jj;  // forward => last
                if (s_idx[base1 + jj] == row) p1 = base1 + jj;
            }
            s_pos[rslot][b0] = p0;
            s_pos[rslot][b1] = p1;
        }
        __syncthreads();

        if (row_ok) {
            bool touched = false;
#pragma unroll
            for (int b = 0; b < BATCH; b++) touched |= (s_pos[rslot][b] >= 0);

            if (!touched) {
#pragma unroll
                for (int b = 0; b < BATCH; b++)
                    stg256(out + ((long long)b * N8 + t8) * 8, v);
            } else {
                const float a  = alpha[row];
                const float na = 1.0f - a;
#pragma unroll
                for (int b = 0; b < BATCH; b++) {
                    f8 w = v;
                    int p2 = s_pos[rslot][b];
                    if (p2 >= 0) {
                        f8 f = ldg256(feat + (long long)p2 * DIM + lane * 8);
                        w.a.x = fmaf(a, f.a.x, na * v.a.x);
                        w.a.y = fmaf(a, f.a.y, na * v.a.y);
                        w.a.z = fmaf(a, f.a.z, na * v.a.z);
                        w.a.w = fmaf(a, f.a.w, na * v.a.w);
                        w.b.x = fmaf(a, f.b.x, na * v.b.x);
                        w.b.y = fmaf(a, f.b.y, na * v.b.y);
                        w.b.z = fmaf(a, f.b.z, na * v.b.z);
                        w.b.w = fmaf(a, f.b.w, na * v.b.w);
                    }
                    stg256(out + ((long long)b * N8 + t8) * 8, w);
                }
            }
        }
    } else if (row_ok) {
        // Untouched CTA: pure 16-way broadcast, 256-bit streaming stores.
#pragma unroll
        for (int b = 0; b < BATCH; b++)
            stg256(out + ((long long)b * N8 + t8) * 8, v);
    }
}

extern "C" void kernel_launch(void* const* d_in, const int* in_sizes, int n_in,
                              void* d_out, int out_size) {
    // 0: nodes (int32/int64)  1: nodes_output f32  2: emb_table f32  3: alpha f32
    const void*  nodes = d_in[0];
    const float* feat  = (const float*)d_in[1];
    const float* emb   = (const float*)d_in[2];
    const float* alpha = (const float*)d_in[3];
    float*       out   = (float*)d_out;

    const int blocks = (ITEMS_TOTAL + ROWS_PER_CTA - 1) / ROWS_PER_CTA;  // 1563
    fused_kernel<<<blocks, THREADS>>>(emb, feat, alpha, nodes, out);
}